// round 15
// baseline (speedup 1.0000x reference)
#include <cuda_runtime.h>
#include <cstdint>

#define SEQ   49
#define CDIM  256
#define NHEAD 8
#define HD    32
#define NWIN  64
#define NB    2048
#define MROWS (NB * SEQ)          // 100352
#define QSCALE 0.17677669529663687f

typedef unsigned long long u64;

// ---------------- scratch (allocation-free rule) ----------------
__device__ float g_q[(size_t)NB * NHEAD * SEQ * HD];
__device__ float g_k[(size_t)NB * NHEAD * SEQ * HD];
__device__ float g_v[(size_t)NB * NHEAD * SEQ * HD];
__device__ float g_att[(size_t)MROWS * CDIM];
__device__ float g_wT[768 * 256];                // qkv_w^T  [N][K], tf32-rounded
__device__ float g_pT[256 * 256];                // proj_w^T [N][K], tf32-rounded
__device__ float g_bm[NWIN * NHEAD * SEQ * SEQ]; // bias+mask, precombined (4.9MB)

__device__ __forceinline__ uint32_t smem_u32(const void* p) {
    uint32_t a;
    asm("{ .reg .u64 t; cvta.to.shared.u64 t, %1; cvt.u32.u64 %0, t; }" : "=r"(a) : "l"(p));
    return a;
}
__device__ __forceinline__ float to_tf32(float x) {
    uint32_t r; asm("cvt.rna.tf32.f32 %0, %1;" : "=r"(r) : "f"(x));
    return __uint_as_float(r);
}
__device__ __forceinline__ void cvt_inplace(uint32_t &u) {
    asm("cvt.rna.tf32.f32 %0, %0;" : "+r"(u));
}
__device__ __forceinline__ void fma2(u64 &acc, u64 a, u64 b) {
    asm("fma.rn.f32x2 %0, %1, %2, %0;" : "+l"(acc) : "l"(a), "l"(b));
}
__device__ __forceinline__ float2 unpack2(u64 v) {
    float2 f;
    asm("mov.b64 {%0, %1}, %2;" : "=f"(f.x), "=f"(f.y) : "l"(v));
    return f;
}
__device__ __forceinline__ u64 pack2(float lo, float hi) {
    u64 v;
    asm("mov.b64 %0, {%1, %2};" : "=l"(v) : "f"(lo), "f"(hi));
    return v;
}
#define CP_ASYNC16(s, g) \
    asm volatile("cp.async.cg.shared.global [%0], [%1], 16;" :: "r"(s), "l"(g) : "memory")

// ldmatrix x4 on b16: loads four 8x8-b16 tiles == fragments of 8x8-f32 tiles.
#define LDSM_X4(d, addr) \
    asm volatile("ldmatrix.sync.aligned.m8n8.x4.shared.b16 {%0,%1,%2,%3}, [%4];" \
        : "=r"((d)[0]), "=r"((d)[1]), "=r"((d)[2]), "=r"((d)[3]) : "r"(addr))

__device__ __forceinline__ void mma_tf32(float* c, const uint32_t* a, uint32_t b0, uint32_t b1) {
    asm volatile(
        "mma.sync.aligned.m16n8k8.row.col.f32.tf32.tf32.f32 "
        "{%0,%1,%2,%3}, {%4,%5,%6,%7}, {%8,%9}, {%0,%1,%2,%3};"
        : "+f"(c[0]), "+f"(c[1]), "+f"(c[2]), "+f"(c[3])
        : "r"(a[0]), "r"(a[1]), "r"(a[2]), "r"(a[3]), "r"(b0), "r"(b1));
}

// ---------------- tensor-core GEMM: C[M x N] = A[M x 256] * BT[N x 256]^T ----
// block 128x128, BK=32, 128 threads = 4 warps (2Mx2N), warp tile 64x64.
// Fragment feed via ldmatrix.x4.b16. MODE 0: A tf32-rounded in-register.
#define BM 128
#define BN 128
#define BK 32
#define LDSW 36                    // BK + 4 pad: conflict-free rows (144B stride)
#define SM_BYTES (2 * (BM + BN) * LDSW * 4)   // 73728

template<int MODE>
__global__ __launch_bounds__(128) void mma_gemm(
    const float* __restrict__ A, const float* __restrict__ BT,
    const float* __restrict__ bias, float* __restrict__ Cout)
{
    extern __shared__ float sm[];
    const uint32_t sbase = smem_u32(sm);

    const int tid = threadIdx.x;
    const int wid = tid >> 5, lane = tid & 31;
    const int wm = wid & 1, wn = wid >> 1;
    const int gid = lane >> 2, tig = lane & 3;
    const int m0 = blockIdx.y * BM, n0 = blockIdx.x * BN;

    const int r8 = lane & 7, i8 = lane >> 3;
    uint32_t aoff[4], boff[4];
    #pragma unroll
    for (int mt = 0; mt < 4; mt++)   // A matrices: {r0-7,k},{r8-15,k},{r0-7,k+4},{r8-15,k+4}
        aoff[mt] = ((wm * 64 + mt * 16 + (i8 & 1) * 8 + r8) * LDSW + (i8 >> 1) * 4) * 4;
    #pragma unroll
    for (int n2 = 0; n2 < 4; n2++)   // B matrices: {r0-7,k},{r0-7,k+4},{r8-15,k},{r8-15,k+4}
        boff[n2] = (uint32_t)(2 * BM * LDSW * 4)
                 + ((wn * 64 + n2 * 16 + (i8 >> 1) * 8 + r8) * LDSW + (i8 & 1) * 4) * 4;

    float acc[4][8][4];
    #pragma unroll
    for (int i = 0; i < 4; i++)
        #pragma unroll
        for (int j = 0; j < 8; j++)
            acc[i][j][0] = acc[i][j][1] = acc[i][j][2] = acc[i][j][3] = 0.f;

    const float* Ag = A + (size_t)m0 * CDIM;
    const float* Bg = BT + (size_t)n0 * CDIM;

    const int ldr = tid >> 3;                // 0..15 (x8 iters -> 128 rows)
    const int ldq = tid & 7;                 // 16B chunk within 128B row

    #define LOAD_CHUNK(cc, buf) do {                                              \
        const uint32_t abase = sbase + ((buf) * BM * LDSW) * 4;                   \
        const uint32_t bbase = sbase + (2 * BM * LDSW + (buf) * BN * LDSW) * 4;   \
        _Pragma("unroll")                                                         \
        for (int i = 0; i < 8; i++) {                                             \
            int r = ldr + i * 16;                                                 \
            CP_ASYNC16(abase + (r * LDSW + ldq * 4) * 4,                          \
                       Ag + (size_t)r * CDIM + (cc) * BK + ldq * 4);              \
            CP_ASYNC16(bbase + (r * LDSW + ldq * 4) * 4,                          \
                       Bg + (size_t)r * CDIM + (cc) * BK + ldq * 4);              \
        }                                                                         \
        asm volatile("cp.async.commit_group;");                                   \
    } while (0)

    LOAD_CHUNK(0, 0);

    #pragma unroll 1
    for (int c = 0; c < CDIM / BK; c++) {
        const int buf = c & 1;
        if (c + 1 < CDIM / BK) {
            LOAD_CHUNK(c + 1, buf ^ 1);
            asm volatile("cp.async.wait_group 1;" ::: "memory");
        } else {
            asm volatile("cp.async.wait_group 0;" ::: "memory");
        }
        __syncthreads();

        const uint32_t ab = sbase + (buf * BM * LDSW) * 4;
        const uint32_t bb = sbase + (buf * BN * LDSW) * 4;
        #pragma unroll
        for (int ks = 0; ks < 4; ks++) {
            const uint32_t kb = ks * 8 * 4;
            uint32_t a[4][4], bfr[4][4];
            #pragma unroll
            for (int mt = 0; mt < 4; mt++)
                LDSM_X4(a[mt], ab + aoff[mt] + kb);
            #pragma unroll
            for (int n2 = 0; n2 < 4; n2++)
                LDSM_X4(bfr[n2], bb + boff[n2] + kb);
            if (MODE == 0) {
                #pragma unroll
                for (int mt = 0; mt < 4; mt++) {
                    cvt_inplace(a[mt][0]); cvt_inplace(a[mt][1]);
                    cvt_inplace(a[mt][2]); cvt_inplace(a[mt][3]);
                }
            }
            #pragma unroll
            for (int nt = 0; nt < 8; nt++) {
                const uint32_t b0 = bfr[nt >> 1][(nt & 1) * 2];
                const uint32_t b1 = bfr[nt >> 1][(nt & 1) * 2 + 1];
                #pragma unroll
                for (int mt = 0; mt < 4; mt++)
                    mma_tf32(acc[mt][nt], a[mt], b0, b1);
            }
        }
        __syncthreads();
    }

    #pragma unroll
    for (int mt = 0; mt < 4; mt++) {
        #pragma unroll
        for (int nt = 0; nt < 8; nt++) {
            const int row = m0 + wm * 64 + mt * 16 + gid;
            const int col = n0 + wn * 64 + nt * 8 + tig * 2;
            const float b0 = __ldg(bias + col), b1 = __ldg(bias + col + 1);
            float2 lo = make_float2(acc[mt][nt][0] + b0, acc[mt][nt][1] + b1);
            float2 hi = make_float2(acc[mt][nt][2] + b0, acc[mt][nt][3] + b1);
            if (MODE == 0) {
                const int which = col >> 8;           // 0=q 1=k 2=v
                float* dbuf = which == 0 ? g_q : (which == 1 ? g_k : g_v);
                if (which == 0) {
                    lo.x *= QSCALE; lo.y *= QSCALE; hi.x *= QSCALE; hi.y *= QSCALE;
                }
                const int cc = col & 255, h = cc >> 5, d = cc & 31;
                {
                    const int b = row / SEQ, n = row - b * SEQ;
                    *(float2*)(dbuf + ((size_t)((b * NHEAD + h) * SEQ + n)) * HD + d) = lo;
                }
                {
                    const int r2 = row + 8;
                    const int b = r2 / SEQ, n = r2 - b * SEQ;
                    *(float2*)(dbuf + ((size_t)((b * NHEAD + h) * SEQ + n)) * HD + d) = hi;
                }
            } else {
                *(float2*)(Cout + (size_t)row * CDIM + col) = lo;
                *(float2*)(Cout + (size_t)(row + 8) * CDIM + col) = hi;
            }
        }
    }
}

// ---------------- weight transpose (+ tf32 round): dst[N][K] = src[K][N] ----
__global__ void transpose_kernel(const float* __restrict__ src, float* __restrict__ dst,
                                 int R, int C)   // src is [R][C]
{
    __shared__ float t[32][33];
    const int bx = blockIdx.x * 32, by = blockIdx.y * 32;
    const int tx = threadIdx.x, ty = threadIdx.y;
    #pragma unroll
    for (int j = 0; j < 32; j += 8)
        t[ty + j][tx] = src[(size_t)(by + ty + j) * C + bx + tx];
    __syncthreads();
    #pragma unroll
    for (int j = 0; j < 32; j += 8)
        dst[(size_t)(bx + ty + j) * R + by + tx] = to_tf32(t[tx][ty + j]);
}

// ---------------- precombine bias gather + mask: g_bm[w][h][49*49] ----------
__global__ void bm_kernel(const float* __restrict__ mask,
                          const float* __restrict__ bias_table,
                          const int* __restrict__ rel_index)
{
    const int w = blockIdx.x >> 3, h = blockIdx.x & 7;
    const float* mrow = mask + (size_t)w * SEQ * SEQ;
    float* dst = g_bm + (size_t)blockIdx.x * SEQ * SEQ;
    for (int i = threadIdx.x; i < SEQ * SEQ; i += blockDim.x)
        dst[i] = bias_table[rel_index[i] * NHEAD + h] + mrow[i];
}

// ---------------- attention: 128 threads / 2 (window,head) pairs -----------
// wid%4 SMSP mapping: 64-thread blocks feed only SMSPs 0,1. Packing two
// head-units per 128-thread block spreads math warps across all 4 SMSPs.
__global__ __launch_bounds__(128) void attn_kernel()
{
    __shared__ float ks[2][SEQ][HD];
    __shared__ float vs[2][SEQ][HD];
    __shared__ float sc[2][SEQ][53];    // bm then scores then probs

    const int tid = threadIdx.x;
    const int sub = tid >> 6;           // which of the 2 head-units
    const int stid = tid & 63;
    const int blk = blockIdx.x * 2 + sub;   // (b*8 + h)
    const int b = blk >> 3, h = blk & 7;
    const int w = b & (NWIN - 1);

    const size_t base = (size_t)blk * SEQ * HD;
    {
        const float4* k4 = (const float4*)(g_k + base);
        const float4* v4 = (const float4*)(g_v + base);
        float4* ks4 = (float4*)ks[sub];
        float4* vs4 = (float4*)vs[sub];
        for (int i = stid; i < SEQ * HD / 4; i += 64) { ks4[i] = k4[i]; vs4[i] = v4[i]; }
        const float* bmg = g_bm + (size_t)(w * NHEAD + h) * SEQ * SEQ;
        for (int i = stid; i < SEQ * SEQ; i += 64)
            sc[sub][i / SEQ][i % SEQ] = bmg[i];
    }
    __syncthreads();

    if (stid < SEQ) {
        const int i = stid;
        u64 q2[HD / 2];
        {
            const ulonglong2* q8 = (const ulonglong2*)(g_q + base + (size_t)i * HD);
            #pragma unroll
            for (int t = 0; t < HD / 4; t++) {
                ulonglong2 p = q8[t];
                q2[2 * t] = p.x; q2[2 * t + 1] = p.y;
            }
        }
        float mx = -1e30f;
        #pragma unroll 7
        for (int j = 0; j < SEQ; j++) {
            u64 a0 = 0ull, a1 = 0ull;            // dual accs: break dep chain
            const ulonglong2* kr = (const ulonglong2*)ks[sub][j];
            #pragma unroll
            for (int t = 0; t < HD / 4; t++) {
                ulonglong2 kp = kr[t];
                fma2(a0, q2[2 * t], kp.x);
                fma2(a1, q2[2 * t + 1], kp.y);
            }
            float2 f0 = unpack2(a0), f1 = unpack2(a1);
            const float s = (f0.x + f0.y) + (f1.x + f1.y) + sc[sub][i][j];
            sc[sub][i][j] = s;
            mx = fmaxf(mx, s);
        }
        float sum = 0.f;
        #pragma unroll 7
        for (int j = 0; j < SEQ; j++) {
            float e = __expf(sc[sub][i][j] - mx);
            sc[sub][i][j] = e;
            sum += e;
        }
        const float inv = 1.f / sum;
        u64 o2[HD / 2];
        #pragma unroll
        for (int t = 0; t < HD / 2; t++) o2[t] = 0ull;
        #pragma unroll 7
        for (int j = 0; j < SEQ; j++) {
            const float p = sc[sub][i][j];
            const u64 pp = pack2(p, p);
            const ulonglong2* vr = (const ulonglong2*)vs[sub][j];
            #pragma unroll
            for (int t = 0; t < HD / 4; t++) {
                ulonglong2 vp = vr[t];
                fma2(o2[2 * t], pp, vp.x);
                fma2(o2[2 * t + 1], pp, vp.y);
            }
        }
        float4* op = (float4*)(g_att + (size_t)(b * SEQ + i) * CDIM + h * HD);
        #pragma unroll
        for (int t = 0; t < HD / 4; t++) {
            float2 a = unpack2(o2[2 * t]), c = unpack2(o2[2 * t + 1]);
            float4 r;   // tf32-rounded so the proj MMA truncation is exact
            r.x = to_tf32(a.x * inv); r.y = to_tf32(a.y * inv);
            r.z = to_tf32(c.x * inv); r.w = to_tf32(c.y * inv);
            op[t] = r;
        }
    }
}

// ---------------- launch ----------------
extern "C" void kernel_launch(void* const* d_in, const int* in_sizes, int n_in,
                              void* d_out, int out_size)
{
    const float* x          = (const float*)d_in[0];
    const float* mask       = (const float*)d_in[1];
    const float* qkv_w      = (const float*)d_in[2];
    const float* qkv_b      = (const float*)d_in[3];
    const float* proj_w     = (const float*)d_in[4];
    const float* proj_b     = (const float*)d_in[5];
    const float* bias_table = (const float*)d_in[6];
    const int*   rel_index  = (const int*)d_in[7];
    float* out = (float*)d_out;

    float *p_att, *p_wT, *p_pT;
    cudaGetSymbolAddress((void**)&p_att, g_att);
    cudaGetSymbolAddress((void**)&p_wT,  g_wT);
    cudaGetSymbolAddress((void**)&p_pT,  g_pT);

    cudaFuncSetAttribute(mma_gemm<0>, cudaFuncAttributeMaxDynamicSharedMemorySize, SM_BYTES);
    cudaFuncSetAttribute(mma_gemm<1>, cudaFuncAttributeMaxDynamicSharedMemorySize, SM_BYTES);

    // 0) transpose+round weights to K-major; combine bias gather + mask
    transpose_kernel<<<dim3(768 / 32, 256 / 32), dim3(32, 8)>>>(qkv_w, p_wT, 256, 768);
    transpose_kernel<<<dim3(256 / 32, 256 / 32), dim3(32, 8)>>>(proj_w, p_pT, 256, 256);
    bm_kernel<<<NWIN * NHEAD, 256>>>(mask, bias_table, rel_index);

    // 1) QKV projection (tensor cores, ldmatrix feed) -> g_q/g_k/g_v
    mma_gemm<0><<<dim3(768 / BN, MROWS / BM), 128, SM_BYTES>>>(x, p_wT, qkv_b, nullptr);

    // 2) windowed attention -> g_att (2 head-units per block, 4 SMSPs)
    attn_kernel<<<NB * NHEAD / 2, 128>>>();

    // 3) output projection -> d_out
    mma_gemm<1><<<dim3(CDIM / BN, MROWS / BM), 128, SM_BYTES>>>(p_att, p_pT, proj_b, out);
}

// round 16
// speedup vs baseline: 1.0295x; 1.0295x over previous
#include <cuda_runtime.h>
#include <cstdint>

#define SEQ   49
#define CDIM  256
#define NHEAD 8
#define HD    32
#define NWIN  64
#define NB    2048
#define MROWS (NB * SEQ)          // 100352
#define QSCALE 0.17677669529663687f

typedef unsigned long long u64;

// ---------------- scratch (allocation-free rule) ----------------
__device__ float g_q[(size_t)NB * NHEAD * SEQ * HD];
__device__ float g_k[(size_t)NB * NHEAD * SEQ * HD];
__device__ float g_v[(size_t)NB * NHEAD * SEQ * HD];
__device__ float g_att[(size_t)MROWS * CDIM];
__device__ float g_wT[768 * 256];                // qkv_w^T  [N][K], tf32-rounded
__device__ float g_pT[256 * 256];                // proj_w^T [N][K], tf32-rounded
__device__ float g_bm[NWIN * NHEAD * SEQ * SEQ]; // bias+mask, precombined (4.9MB)

__device__ __forceinline__ uint32_t smem_u32(const void* p) {
    uint32_t a;
    asm("{ .reg .u64 t; cvta.to.shared.u64 t, %1; cvt.u32.u64 %0, t; }" : "=r"(a) : "l"(p));
    return a;
}
__device__ __forceinline__ float to_tf32(float x) {
    uint32_t r; asm("cvt.rna.tf32.f32 %0, %1;" : "=r"(r) : "f"(x));
    return __uint_as_float(r);
}
__device__ __forceinline__ void cvt_inplace(uint32_t &u) {
    asm("cvt.rna.tf32.f32 %0, %0;" : "+r"(u));
}
#define CP_ASYNC16(s, g) \
    asm volatile("cp.async.cg.shared.global [%0], [%1], 16;" :: "r"(s), "l"(g) : "memory")

// ldmatrix x4 on b16: loads four 8x8-b16 tiles == fragments of 8x8-f32 tiles.
#define LDSM_X4(d, addr) \
    asm volatile("ldmatrix.sync.aligned.m8n8.x4.shared.b16 {%0,%1,%2,%3}, [%4];" \
        : "=r"((d)[0]), "=r"((d)[1]), "=r"((d)[2]), "=r"((d)[3]) : "r"(addr))

__device__ __forceinline__ void mma_tf32(float* c, const uint32_t* a, uint32_t b0, uint32_t b1) {
    asm volatile(
        "mma.sync.aligned.m16n8k8.row.col.f32.tf32.tf32.f32 "
        "{%0,%1,%2,%3}, {%4,%5,%6,%7}, {%8,%9}, {%0,%1,%2,%3};"
        : "+f"(c[0]), "+f"(c[1]), "+f"(c[2]), "+f"(c[3])
        : "r"(a[0]), "r"(a[1]), "r"(a[2]), "r"(a[3]), "r"(b0), "r"(b1));
}

// ---------------- tensor-core GEMM (unchanged from best round) -------------
#define BM 128
#define BN 128
#define BK 32
#define LDSW 36
#define SM_BYTES (2 * (BM + BN) * LDSW * 4)   // 73728

template<int MODE>
__global__ __launch_bounds__(128) void mma_gemm(
    const float* __restrict__ A, const float* __restrict__ BT,
    const float* __restrict__ bias, float* __restrict__ Cout)
{
    extern __shared__ float sm[];
    const uint32_t sbase = smem_u32(sm);

    const int tid = threadIdx.x;
    const int wid = tid >> 5, lane = tid & 31;
    const int wm = wid & 1, wn = wid >> 1;
    const int gid = lane >> 2, tig = lane & 3;
    const int m0 = blockIdx.y * BM, n0 = blockIdx.x * BN;

    const int r8 = lane & 7, i8 = lane >> 3;
    uint32_t aoff[4], boff[4];
    #pragma unroll
    for (int mt = 0; mt < 4; mt++)
        aoff[mt] = ((wm * 64 + mt * 16 + (i8 & 1) * 8 + r8) * LDSW + (i8 >> 1) * 4) * 4;
    #pragma unroll
    for (int n2 = 0; n2 < 4; n2++)
        boff[n2] = (uint32_t)(2 * BM * LDSW * 4)
                 + ((wn * 64 + n2 * 16 + (i8 >> 1) * 8 + r8) * LDSW + (i8 & 1) * 4) * 4;

    float acc[4][8][4];
    #pragma unroll
    for (int i = 0; i < 4; i++)
        #pragma unroll
        for (int j = 0; j < 8; j++)
            acc[i][j][0] = acc[i][j][1] = acc[i][j][2] = acc[i][j][3] = 0.f;

    const float* Ag = A + (size_t)m0 * CDIM;
    const float* Bg = BT + (size_t)n0 * CDIM;

    const int ldr = tid >> 3;
    const int ldq = tid & 7;

    #define LOAD_CHUNK(cc, buf) do {                                              \
        const uint32_t abase = sbase + ((buf) * BM * LDSW) * 4;                   \
        const uint32_t bbase = sbase + (2 * BM * LDSW + (buf) * BN * LDSW) * 4;   \
        _Pragma("unroll")                                                         \
        for (int i = 0; i < 8; i++) {                                             \
            int r = ldr + i * 16;                                                 \
            CP_ASYNC16(abase + (r * LDSW + ldq * 4) * 4,                          \
                       Ag + (size_t)r * CDIM + (cc) * BK + ldq * 4);              \
            CP_ASYNC16(bbase + (r * LDSW + ldq * 4) * 4,                          \
                       Bg + (size_t)r * CDIM + (cc) * BK + ldq * 4);              \
        }                                                                         \
        asm volatile("cp.async.commit_group;");                                   \
    } while (0)

    LOAD_CHUNK(0, 0);

    #pragma unroll 1
    for (int c = 0; c < CDIM / BK; c++) {
        const int buf = c & 1;
        if (c + 1 < CDIM / BK) {
            LOAD_CHUNK(c + 1, buf ^ 1);
            asm volatile("cp.async.wait_group 1;" ::: "memory");
        } else {
            asm volatile("cp.async.wait_group 0;" ::: "memory");
        }
        __syncthreads();

        const uint32_t ab = sbase + (buf * BM * LDSW) * 4;
        const uint32_t bb = sbase + (buf * BN * LDSW) * 4;
        #pragma unroll
        for (int ks = 0; ks < 4; ks++) {
            const uint32_t kb = ks * 8 * 4;
            uint32_t a[4][4], bfr[4][4];
            #pragma unroll
            for (int mt = 0; mt < 4; mt++)
                LDSM_X4(a[mt], ab + aoff[mt] + kb);
            #pragma unroll
            for (int n2 = 0; n2 < 4; n2++)
                LDSM_X4(bfr[n2], bb + boff[n2] + kb);
            if (MODE == 0) {
                #pragma unroll
                for (int mt = 0; mt < 4; mt++) {
                    cvt_inplace(a[mt][0]); cvt_inplace(a[mt][1]);
                    cvt_inplace(a[mt][2]); cvt_inplace(a[mt][3]);
                }
            }
            #pragma unroll
            for (int nt = 0; nt < 8; nt++) {
                const uint32_t b0 = bfr[nt >> 1][(nt & 1) * 2];
                const uint32_t b1 = bfr[nt >> 1][(nt & 1) * 2 + 1];
                #pragma unroll
                for (int mt = 0; mt < 4; mt++)
                    mma_tf32(acc[mt][nt], a[mt], b0, b1);
            }
        }
        __syncthreads();
    }

    #pragma unroll
    for (int mt = 0; mt < 4; mt++) {
        #pragma unroll
        for (int nt = 0; nt < 8; nt++) {
            const int row = m0 + wm * 64 + mt * 16 + gid;
            const int col = n0 + wn * 64 + nt * 8 + tig * 2;
            const float b0 = __ldg(bias + col), b1 = __ldg(bias + col + 1);
            float2 lo = make_float2(acc[mt][nt][0] + b0, acc[mt][nt][1] + b1);
            float2 hi = make_float2(acc[mt][nt][2] + b0, acc[mt][nt][3] + b1);
            if (MODE == 0) {
                const int which = col >> 8;
                float* dbuf = which == 0 ? g_q : (which == 1 ? g_k : g_v);
                if (which == 0) {
                    lo.x *= QSCALE; lo.y *= QSCALE; hi.x *= QSCALE; hi.y *= QSCALE;
                }
                const int cc = col & 255, h = cc >> 5, d = cc & 31;
                {
                    const int b = row / SEQ, n = row - b * SEQ;
                    *(float2*)(dbuf + ((size_t)((b * NHEAD + h) * SEQ + n)) * HD + d) = lo;
                }
                {
                    const int r2 = row + 8;
                    const int b = r2 / SEQ, n = r2 - b * SEQ;
                    *(float2*)(dbuf + ((size_t)((b * NHEAD + h) * SEQ + n)) * HD + d) = hi;
                }
            } else {
                *(float2*)(Cout + (size_t)row * CDIM + col) = lo;
                *(float2*)(Cout + (size_t)(row + 8) * CDIM + col) = hi;
            }
        }
    }
}

// ---------------- weight transpose (+ tf32 round) ---------------------------
__global__ void transpose_kernel(const float* __restrict__ src, float* __restrict__ dst,
                                 int R, int C)
{
    __shared__ float t[32][33];
    const int bx = blockIdx.x * 32, by = blockIdx.y * 32;
    const int tx = threadIdx.x, ty = threadIdx.y;
    #pragma unroll
    for (int j = 0; j < 32; j += 8)
        t[ty + j][tx] = src[(size_t)(by + ty + j) * C + bx + tx];
    __syncthreads();
    #pragma unroll
    for (int j = 0; j < 32; j += 8)
        dst[(size_t)(bx + ty + j) * R + by + tx] = to_tf32(t[tx][ty + j]);
}

// ---------------- precombine bias gather + mask -----------------------------
__global__ void bm_kernel(const float* __restrict__ mask,
                          const float* __restrict__ bias_table,
                          const int* __restrict__ rel_index)
{
    const int w = blockIdx.x >> 3, h = blockIdx.x & 7;
    const float* mrow = mask + (size_t)w * SEQ * SEQ;
    float* dst = g_bm + (size_t)blockIdx.x * SEQ * SEQ;
    for (int i = threadIdx.x; i < SEQ * SEQ; i += blockDim.x)
        dst[i] = bias_table[rel_index[i] * NHEAD + h] + mrow[i];
}

// ---------------- tensor-core attention -------------------------------------
// Per (window,head) unit: 2 warps split M (rows). S=Q*K^T via m16n8k8 tf32,
// softmax in fragment registers (row owned by a lane quad), P*V via MMA with
// V staged transposed. 2 units per 128-thread CTA; smem buffers reused
// across phases (Q->VT, bm->P).
#define USMEM 8960               // floats per unit: Q/VT 2304 + K 2304 + P/bm 4352
#define ATTN_SMEM (2 * USMEM * 4)   // 71680 B

__global__ __launch_bounds__(128) void attn_kernel()
{
    extern __shared__ float asmem[];
    const int tid = threadIdx.x;
    const int sub = tid >> 6, stid = tid & 63;
    float* Qs = asmem + sub * USMEM;     // [64][36]; later VT [32][68]
    float* Ks = Qs + 2304;               // [64][36] (rows 49-63 garbage, masked)
    float* Pb = Ks + 2304;               // bm [49][53] then P [64][68]

    const int blk = blockIdx.x * 2 + sub;
    const int b = blk >> 3, h = blk & 7;
    const int w = b & (NWIN - 1);
    const size_t base = (size_t)blk * SEQ * HD;

    // ---- stage Q, K (rna-rounded), bm ----
    {
        const float4* q4 = (const float4*)(g_q + base);
        const float4* k4 = (const float4*)(g_k + base);
        for (int i = stid; i < SEQ * 8; i += 64) {
            int r = i >> 3, c = i & 7;
            float4 qv = q4[i], kv = k4[i];
            qv.x = to_tf32(qv.x); qv.y = to_tf32(qv.y);
            qv.z = to_tf32(qv.z); qv.w = to_tf32(qv.w);
            kv.x = to_tf32(kv.x); kv.y = to_tf32(kv.y);
            kv.z = to_tf32(kv.z); kv.w = to_tf32(kv.w);
            *(float4*)(Qs + r * 36 + c * 4) = qv;
            *(float4*)(Ks + r * 36 + c * 4) = kv;
        }
        const float* bmg = g_bm + (size_t)(w * NHEAD + h) * SEQ * SEQ;
        for (int i = stid; i < SEQ * SEQ; i += 64)
            Pb[(i / SEQ) * 53 + (i % SEQ)] = bmg[i];
    }
    __syncthreads();

    const int wm = (tid >> 5) & 1;       // warp within unit (M half)
    const int lane = tid & 31, gid = lane >> 2, tig = lane & 3;
    const int r8 = lane & 7, i8 = lane >> 3;
    const uint32_t qb = smem_u32(Qs), kb = smem_u32(Ks), pbb = smem_u32(Pb);

    // ---- S = Q K^T  (M 64 split 2 warps, N 56 in 7 n8-tiles, K 32) ----
    float acc[2][7][4];
    #pragma unroll
    for (int i = 0; i < 2; i++)
        #pragma unroll
        for (int j = 0; j < 7; j++)
            acc[i][j][0] = acc[i][j][1] = acc[i][j][2] = acc[i][j][3] = 0.f;

    #pragma unroll
    for (int ks = 0; ks < 4; ks++) {
        const uint32_t kbts = ks * 32;
        uint32_t a[2][4], bf[4][4];
        #pragma unroll
        for (int mt = 0; mt < 2; mt++)
            LDSM_X4(a[mt], qb + ((wm * 32 + mt * 16 + (i8 & 1) * 8 + r8) * 36
                                 + (i8 >> 1) * 4) * 4 + kbts);
        #pragma unroll
        for (int n2 = 0; n2 < 4; n2++)
            LDSM_X4(bf[n2], kb + ((n2 * 16 + (i8 >> 1) * 8 + r8) * 36
                                  + (i8 & 1) * 4) * 4 + kbts);
        #pragma unroll
        for (int nt = 0; nt < 7; nt++) {
            const uint32_t b0 = bf[nt >> 1][(nt & 1) * 2];
            const uint32_t b1 = bf[nt >> 1][(nt & 1) * 2 + 1];
            mma_tf32(acc[0][nt], a[0], b0, b1);
            mma_tf32(acc[1][nt], a[1], b0, b1);
        }
    }
    // ---- add bias+mask (bm in Pb, stride 53) ----
    #pragma unroll
    for (int mt = 0; mt < 2; mt++) {
        const int row = wm * 32 + mt * 16 + gid;
        #pragma unroll
        for (int nt = 0; nt < 7; nt++) {
            const int col = nt * 8 + tig * 2;
            if (col < SEQ) {
                acc[mt][nt][0] += Pb[row * 53 + col];
                acc[mt][nt][2] += Pb[(row + 8) * 53 + col];
            }
            if (col + 1 < SEQ) {
                acc[mt][nt][1] += Pb[row * 53 + col + 1];
                acc[mt][nt][3] += Pb[(row + 8) * 53 + col + 1];
            }
        }
    }
    __syncthreads();    // bm consumed, Q consumed -> buffers reusable

    // ---- stage V transposed into Qs as VT [32][68] (rna), zero pad cols ----
    {
        const float4* v4 = (const float4*)(g_v + base);
        for (int i = stid; i < SEQ * 8; i += 64) {
            int j = i >> 3, d4 = i & 7;
            float4 vv = v4[i];
            Qs[(d4 * 4 + 0) * 68 + j] = to_tf32(vv.x);
            Qs[(d4 * 4 + 1) * 68 + j] = to_tf32(vv.y);
            Qs[(d4 * 4 + 2) * 68 + j] = to_tf32(vv.z);
            Qs[(d4 * 4 + 3) * 68 + j] = to_tf32(vv.w);
        }
        for (int i = stid; i < 32 * 15; i += 64) {
            int d = i / 15, c = SEQ + i % 15;
            Qs[d * 68 + c] = 0.f;
        }
    }

    // ---- softmax in fragment registers; store unnormalized P (stride 68) ----
    float inv[4];
    #pragma unroll
    for (int s = 0; s < 4; s++) {
        const int mt = s >> 1, hf = s & 1;
        const int row = wm * 32 + mt * 16 + gid + hf * 8;
        float m = -1e30f;
        #pragma unroll
        for (int nt = 0; nt < 7; nt++) {
            const int col = nt * 8 + tig * 2;
            if (col < SEQ)     m = fmaxf(m, acc[mt][nt][hf * 2]);
            if (col + 1 < SEQ) m = fmaxf(m, acc[mt][nt][hf * 2 + 1]);
        }
        m = fmaxf(m, __shfl_xor_sync(0xffffffffu, m, 1));
        m = fmaxf(m, __shfl_xor_sync(0xffffffffu, m, 2));
        float sum = 0.f;
        #pragma unroll
        for (int nt = 0; nt < 7; nt++) {
            const int col = nt * 8 + tig * 2;
            float e0 = (col < SEQ)     ? __expf(acc[mt][nt][hf * 2] - m)     : 0.f;
            float e1 = (col + 1 < SEQ) ? __expf(acc[mt][nt][hf * 2 + 1] - m) : 0.f;
            sum += e0 + e1;
            *(float2*)(Pb + row * 68 + col) = make_float2(to_tf32(e0), to_tf32(e1));
        }
        *(float2*)(Pb + row * 68 + 56 + tig * 2) = make_float2(0.f, 0.f);  // pad k 56-63
        sum += __shfl_xor_sync(0xffffffffu, sum, 1);
        sum += __shfl_xor_sync(0xffffffffu, sum, 2);
        inv[s] = 1.f / sum;
    }
    __syncthreads();    // VT staged by all, P fully written

    // ---- O = P * V  (M 64 split, N 32 in 4 n8, K 64 in 8 k8) ----
    float o[2][4][4];
    #pragma unroll
    for (int i = 0; i < 2; i++)
        #pragma unroll
        for (int j = 0; j < 4; j++)
            o[i][j][0] = o[i][j][1] = o[i][j][2] = o[i][j][3] = 0.f;

    #pragma unroll
    for (int ks = 0; ks < 8; ks++) {
        const uint32_t kbts = ks * 32;
        uint32_t pa[2][4], vb[2][4];
        #pragma unroll
        for (int mt = 0; mt < 2; mt++)
            LDSM_X4(pa[mt], pbb + ((wm * 32 + mt * 16 + (i8 & 1) * 8 + r8) * 68
                                   + (i8 >> 1) * 4) * 4 + kbts);
        #pragma unroll
        for (int n2 = 0; n2 < 2; n2++)
            LDSM_X4(vb[n2], qb + ((n2 * 16 + (i8 >> 1) * 8 + r8) * 68
                                  + (i8 & 1) * 4) * 4 + kbts);
        #pragma unroll
        for (int nt = 0; nt < 4; nt++) {
            const uint32_t b0 = vb[nt >> 1][(nt & 1) * 2];
            const uint32_t b1 = vb[nt >> 1][(nt & 1) * 2 + 1];
            mma_tf32(o[0][nt], pa[0], b0, b1);
            mma_tf32(o[1][nt], pa[1], b0, b1);
        }
    }

    // ---- epilogue: scale by inv, rna-round (proj consumes tf32), store ----
    #pragma unroll
    for (int mt = 0; mt < 2; mt++) {
        #pragma unroll
        for (int nt = 0; nt < 4; nt++) {
            const int row = wm * 32 + mt * 16 + gid;
            const int col = nt * 8 + tig * 2;
            if (row < SEQ) {
                const float iv = inv[mt * 2];
                *(float2*)(g_att + (size_t)(b * SEQ + row) * CDIM + h * HD + col) =
                    make_float2(to_tf32(o[mt][nt][0] * iv), to_tf32(o[mt][nt][1] * iv));
            }
            if (row + 8 < SEQ) {
                const float iv = inv[mt * 2 + 1];
                *(float2*)(g_att + (size_t)(b * SEQ + row + 8) * CDIM + h * HD + col) =
                    make_float2(to_tf32(o[mt][nt][2] * iv), to_tf32(o[mt][nt][3] * iv));
            }
        }
    }
}

// ---------------- launch ----------------
extern "C" void kernel_launch(void* const* d_in, const int* in_sizes, int n_in,
                              void* d_out, int out_size)
{
    const float* x          = (const float*)d_in[0];
    const float* mask       = (const float*)d_in[1];
    const float* qkv_w      = (const float*)d_in[2];
    const float* qkv_b      = (const float*)d_in[3];
    const float* proj_w     = (const float*)d_in[4];
    const float* proj_b     = (const float*)d_in[5];
    const float* bias_table = (const float*)d_in[6];
    const int*   rel_index  = (const int*)d_in[7];
    float* out = (float*)d_out;

    float *p_att, *p_wT, *p_pT;
    cudaGetSymbolAddress((void**)&p_att, g_att);
    cudaGetSymbolAddress((void**)&p_wT,  g_wT);
    cudaGetSymbolAddress((void**)&p_pT,  g_pT);

    cudaFuncSetAttribute(mma_gemm<0>, cudaFuncAttributeMaxDynamicSharedMemorySize, SM_BYTES);
    cudaFuncSetAttribute(mma_gemm<1>, cudaFuncAttributeMaxDynamicSharedMemorySize, SM_BYTES);
    cudaFuncSetAttribute(attn_kernel, cudaFuncAttributeMaxDynamicSharedMemorySize, ATTN_SMEM);

    // 0) transpose+round weights; combine bias gather + mask
    transpose_kernel<<<dim3(768 / 32, 256 / 32), dim3(32, 8)>>>(qkv_w, p_wT, 256, 768);
    transpose_kernel<<<dim3(256 / 32, 256 / 32), dim3(32, 8)>>>(proj_w, p_pT, 256, 256);
    bm_kernel<<<NWIN * NHEAD, 256>>>(mask, bias_table, rel_index);

    // 1) QKV projection -> g_q/g_k/g_v
    mma_gemm<0><<<dim3(768 / BN, MROWS / BM), 128, SM_BYTES>>>(x, p_wT, qkv_b, nullptr);

    // 2) windowed attention (tensor cores) -> g_att
    attn_kernel<<<NB * NHEAD / 2, 128, ATTN_SMEM>>>();

    // 3) output projection -> d_out
    mma_gemm<1><<<dim3(CDIM / BN, MROWS / BM), 128, SM_BYTES>>>(p_att, p_pT, proj_b, out);
}